// round 3
// baseline (speedup 1.0000x reference)
#include <cuda_runtime.h>
#include <cuda_bf16.h>
#include <math.h>

// Problem constants
#define BB 8
#define SS 512
#define DD 1024
#define FF 4096
#define EE 8
#define HH 16
#define HDIM 64
#define NTOK 4096              // B*S
#define NSLOT 8192             // NTOK * top2
#define MAXPAD 9216            // 8192 + 8*128 padding
#define MAXMT 72               // MAXPAD/128

// ---------------- scratch (device globals; no allocation) ----------------
__device__ float g_hln [NTOK * DD];
__device__ float g_qkv [NTOK * 3 * DD];
__device__ float g_attn[NTOK * DD];
__device__ float g_xres[NTOK * DD];
__device__ float g_moein[NTOK * DD];
__device__ float g_h1  [MAXPAD * FF];     // 151 MB
__device__ float g_y   [MAXPAD * DD];     // 36 MB

__device__ int   g_top_e[NSLOT];
__device__ float g_top_w[NSLOT];
__device__ int   g_counts[EE];
__device__ int   g_pad_off[EE + 1];
__device__ int   g_tile_expert[MAXMT];
__device__ int   g_n_mtiles;
__device__ int   g_tok_of_slot[MAXPAD];
__device__ int   g_slot_of[NSLOT];

// ---------------- helpers ----------------
__device__ __forceinline__ float gelu_tanh(float v) {
    const float c = 0.7978845608028654f;
    float u = c * (v + 0.044715f * v * v * v);
    return 0.5f * v * (1.0f + tanhf(u));
}

// ---------------- LayerNorm (one row per block) ----------------
__global__ __launch_bounds__(256)
void ln_kernel(const float* __restrict__ x, const float* __restrict__ g,
               const float* __restrict__ b, float* __restrict__ y) {
    int n = blockIdx.x;
    int tid = threadIdx.x;                 // 256 threads, 4 floats each
    const float4* xr = (const float4*)(x + (size_t)n * DD);
    float4 v = xr[tid];
    float s  = v.x + v.y + v.z + v.w;
    float sq = v.x*v.x + v.y*v.y + v.z*v.z + v.w*v.w;

    __shared__ float red[2][8];
    int lane = tid & 31, wid = tid >> 5;
    #pragma unroll
    for (int o = 16; o > 0; o >>= 1) {
        s  += __shfl_down_sync(0xffffffffu, s,  o);
        sq += __shfl_down_sync(0xffffffffu, sq, o);
    }
    if (lane == 0) { red[0][wid] = s; red[1][wid] = sq; }
    __syncthreads();
    if (wid == 0) {
        float a = (lane < 8) ? red[0][lane] : 0.f;
        float c = (lane < 8) ? red[1][lane] : 0.f;
        #pragma unroll
        for (int o = 4; o > 0; o >>= 1) {
            a += __shfl_down_sync(0xffffffffu, a, o);
            c += __shfl_down_sync(0xffffffffu, c, o);
        }
        if (lane == 0) { red[0][0] = a; red[1][0] = c; }
    }
    __syncthreads();
    float mean = red[0][0] * (1.0f / DD);
    float var  = red[1][0] * (1.0f / DD) - mean * mean;
    float rstd = rsqrtf(var + 1e-5f);

    float4 gv = ((const float4*)g)[tid];
    float4 bv = ((const float4*)b)[tid];
    float4 o;
    o.x = (v.x - mean) * rstd * gv.x + bv.x;
    o.y = (v.y - mean) * rstd * gv.y + bv.y;
    o.z = (v.z - mean) * rstd * gv.z + bv.z;
    o.w = (v.w - mean) * rstd * gv.w + bv.w;
    ((float4*)(y + (size_t)n * DD))[tid] = o;
}

// ---------------- SGEMM 128x128x16, 256 thr, 8x8 per thread ----------------
template<bool RESID>
__global__ __launch_bounds__(256)
void sgemm_kernel(const float* __restrict__ A, const float* __restrict__ B,
                  const float* __restrict__ R, float* __restrict__ C,
                  int M, int N, int K) {
    __shared__ float As[16][136];
    __shared__ float Bs[16][128];
    int tid = threadIdx.x;
    int bm = blockIdx.y * 128, bn = blockIdx.x * 128;
    int tx = tid & 15, ty = tid >> 4;
    int arow = tid >> 2;                 // 0..63
    int ac   = (tid & 3) << 2;           // 0,4,8,12
    int brow = tid >> 5;                 // 0..7
    int bc   = (tid & 31) << 2;

    const float* Ap0 = A + (size_t)(bm + arow) * K;
    const float* Ap1 = A + (size_t)(bm + arow + 64) * K;

    float cacc[8][8];
    #pragma unroll
    for (int i = 0; i < 8; i++)
        #pragma unroll
        for (int j = 0; j < 8; j++) cacc[i][j] = 0.f;

    for (int k0 = 0; k0 < K; k0 += 16) {
        float4 a0 = *(const float4*)(Ap0 + k0 + ac);
        float4 a1 = *(const float4*)(Ap1 + k0 + ac);
        As[ac+0][arow] = a0.x; As[ac+1][arow] = a0.y;
        As[ac+2][arow] = a0.z; As[ac+3][arow] = a0.w;
        As[ac+0][arow+64] = a1.x; As[ac+1][arow+64] = a1.y;
        As[ac+2][arow+64] = a1.z; As[ac+3][arow+64] = a1.w;
        float4 b0 = *(const float4*)(B + (size_t)(k0 + brow) * N + bn + bc);
        float4 b1 = *(const float4*)(B + (size_t)(k0 + brow + 8) * N + bn + bc);
        *(float4*)&Bs[brow][bc]   = b0;
        *(float4*)&Bs[brow+8][bc] = b1;
        __syncthreads();
        #pragma unroll
        for (int k = 0; k < 16; ++k) {
            float ar[8], br[8];
            #pragma unroll
            for (int i = 0; i < 8; i++) ar[i] = As[k][ty*8 + i];
            #pragma unroll
            for (int j = 0; j < 8; j++) br[j] = Bs[k][tx*8 + j];
            #pragma unroll
            for (int i = 0; i < 8; i++)
                #pragma unroll
                for (int j = 0; j < 8; j++)
                    cacc[i][j] += ar[i] * br[j];
        }
        __syncthreads();
    }

    #pragma unroll
    for (int i = 0; i < 8; i++) {
        int row = bm + ty*8 + i;
        #pragma unroll
        for (int j = 0; j < 8; j++) {
            int col = bn + tx*8 + j;
            float v = cacc[i][j];
            if (RESID) v += R[(size_t)row * N + col];
            C[(size_t)row * N + col] = v;
        }
    }
}

// ---------------- grouped MoE GEMM ----------------
// STAGE1: A rows indirect (moe_in via tok_of_slot), B=w1[e], epilogue gelu(.+b1)
// STAGE2: A = h1 rows direct,                       B=w2[e], epilogue .+b2
template<bool STAGE1>
__global__ __launch_bounds__(256)
void moe_gemm_kernel(const float* __restrict__ Abase, const float* __restrict__ Wbase,
                     const float* __restrict__ biasbase, float* __restrict__ Cbase,
                     int N, int K) {
    int mt = blockIdx.y;
    if (mt >= g_n_mtiles) return;
    int e = g_tile_expert[mt];
    const float* B    = Wbase + (size_t)e * K * N;
    const float* bias = biasbase + (size_t)e * N;

    __shared__ float As[16][136];
    __shared__ float Bs[16][128];
    int tid = threadIdx.x;
    int bm = mt * 128, bn = blockIdx.x * 128;
    int tx = tid & 15, ty = tid >> 4;
    int arow = tid >> 2;
    int ac   = (tid & 3) << 2;
    int brow = tid >> 5;
    int bc   = (tid & 31) << 2;

    const float *Ap0, *Ap1;
    if (STAGE1) {
        Ap0 = Abase + (size_t)g_tok_of_slot[bm + arow] * K;
        Ap1 = Abase + (size_t)g_tok_of_slot[bm + arow + 64] * K;
    } else {
        Ap0 = Abase + (size_t)(bm + arow) * K;
        Ap1 = Abase + (size_t)(bm + arow + 64) * K;
    }

    float cacc[8][8];
    #pragma unroll
    for (int i = 0; i < 8; i++)
        #pragma unroll
        for (int j = 0; j < 8; j++) cacc[i][j] = 0.f;

    for (int k0 = 0; k0 < K; k0 += 16) {
        float4 a0 = *(const float4*)(Ap0 + k0 + ac);
        float4 a1 = *(const float4*)(Ap1 + k0 + ac);
        As[ac+0][arow] = a0.x; As[ac+1][arow] = a0.y;
        As[ac+2][arow] = a0.z; As[ac+3][arow] = a0.w;
        As[ac+0][arow+64] = a1.x; As[ac+1][arow+64] = a1.y;
        As[ac+2][arow+64] = a1.z; As[ac+3][arow+64] = a1.w;
        float4 b0 = *(const float4*)(B + (size_t)(k0 + brow) * N + bn + bc);
        float4 b1 = *(const float4*)(B + (size_t)(k0 + brow + 8) * N + bn + bc);
        *(float4*)&Bs[brow][bc]   = b0;
        *(float4*)&Bs[brow+8][bc] = b1;
        __syncthreads();
        #pragma unroll
        for (int k = 0; k < 16; ++k) {
            float ar[8], br[8];
            #pragma unroll
            for (int i = 0; i < 8; i++) ar[i] = As[k][ty*8 + i];
            #pragma unroll
            for (int j = 0; j < 8; j++) br[j] = Bs[k][tx*8 + j];
            #pragma unroll
            for (int i = 0; i < 8; i++)
                #pragma unroll
                for (int j = 0; j < 8; j++)
                    cacc[i][j] += ar[i] * br[j];
        }
        __syncthreads();
    }

    #pragma unroll
    for (int i = 0; i < 8; i++) {
        int row = bm + ty*8 + i;
        #pragma unroll
        for (int j = 0; j < 8; j++) {
            int col = bn + tx*8 + j;
            float v = cacc[i][j] + bias[col];
            if (STAGE1) v = gelu_tanh(v);
            Cbase[(size_t)row * N + col] = v;
        }
    }
}

// ---------------- causal flash attention ----------------
// grid (qt=8, h=16, b=8), 64 threads; thread t owns query qt*64+t.
__global__ __launch_bounds__(64)
void attn_kernel(const float* __restrict__ qkv, float* __restrict__ o) {
    __shared__ float KV[64][64];
    __shared__ float Sb[64][65];
    int qt = blockIdx.x, h = blockIdx.y, b = blockIdx.z;
    int t = threadIdx.x;
    int q = qt * 64 + t;
    const float* qrow = qkv + (size_t)(b * SS + q) * (3 * DD) + h * HDIM;

    float qreg[64];
    #pragma unroll
    for (int d = 0; d < 64; d++) qreg[d] = qrow[d];
    float acc[64];
    #pragma unroll
    for (int d = 0; d < 64; d++) acc[d] = 0.f;
    float m = -1e30f, l = 0.f;
    const float scale = 0.125f;   // 64^-0.5

    for (int kt = 0; kt <= qt; ++kt) {
        // K tile
        for (int i = t; i < 1024; i += 64) {
            int j = i * 4; int kk = j >> 6; int d = j & 63;
            *(float4*)&KV[kk][d] = *(const float4*)(
                qkv + (size_t)(b * SS + kt * 64 + kk) * (3 * DD) + DD + h * HDIM + d);
        }
        __syncthreads();
        int kmax = (kt == qt) ? (t + 1) : 64;
        float tmax = -1e30f;
        for (int kk = 0; kk < kmax; ++kk) {
            float s = 0.f;
            #pragma unroll
            for (int d = 0; d < 64; d++) s += qreg[d] * KV[kk][d];
            s *= scale;
            Sb[t][kk] = s;
            tmax = fmaxf(tmax, s);
        }
        float mn = fmaxf(m, tmax);
        float corr = __expf(m - mn);
        #pragma unroll
        for (int d = 0; d < 64; d++) acc[d] *= corr;
        l *= corr;
        m = mn;
        __syncthreads();               // everyone done with K
        // V tile (reuse KV)
        for (int i = t; i < 1024; i += 64) {
            int j = i * 4; int kk = j >> 6; int d = j & 63;
            *(float4*)&KV[kk][d] = *(const float4*)(
                qkv + (size_t)(b * SS + kt * 64 + kk) * (3 * DD) + 2 * DD + h * HDIM + d);
        }
        __syncthreads();
        for (int kk = 0; kk < kmax; ++kk) {
            float p = __expf(Sb[t][kk] - m);
            l += p;
            #pragma unroll
            for (int d = 0; d < 64; d++) acc[d] += p * KV[kk][d];
        }
        __syncthreads();               // before next tile overwrites KV
    }
    float inv = 1.f / l;
    float* orow = o + (size_t)(b * SS + q) * DD + h * HDIM;
    #pragma unroll
    for (int d = 0; d < 64; d++) orow[d] = acc[d] * inv;
}

// ---------------- gate: logits + top-2 + renormalized weights ----------------
// one warp per token; 4 warps per block
__global__ __launch_bounds__(128)
void gate_kernel(const float* __restrict__ moe_in, const float* __restrict__ w_gate) {
    int lane = threadIdx.x & 31, wid = threadIdx.x >> 5;
    int n = blockIdx.x * 4 + wid;
    float acc[EE];
    #pragma unroll
    for (int e = 0; e < EE; e++) acc[e] = 0.f;
    const float* xr = moe_in + (size_t)n * DD;
    for (int d = lane; d < DD; d += 32) {
        float xv = xr[d];
        const float* wg = w_gate + (size_t)d * EE;
        #pragma unroll
        for (int e = 0; e < EE; e++) acc[e] += xv * wg[e];
    }
    #pragma unroll
    for (int e = 0; e < EE; e++) {
        #pragma unroll
        for (int o = 16; o > 0; o >>= 1)
            acc[e] += __shfl_down_sync(0xffffffffu, acc[e], o);
    }
    if (lane == 0) {
        int i0 = 0;
        #pragma unroll
        for (int e = 1; e < EE; e++) if (acc[e] > acc[i0]) i0 = e;
        int i1 = (i0 == 0) ? 1 : 0;
        #pragma unroll
        for (int e = 0; e < EE; e++)
            if (e != i0 && acc[e] > acc[i1]) i1 = e;
        // renormalized top-2 softmax weights: w0 = 1/(1+exp(l1-l0))
        float w0 = 1.f / (1.f + __expf(acc[i1] - acc[i0]));
        g_top_e[2*n]   = i0;  g_top_e[2*n+1]   = i1;
        g_top_w[2*n]   = w0;  g_top_w[2*n+1]   = 1.f - w0;
    }
}

// ---------------- routing: counts -> padded offsets -> stable compact ----------------
__global__ void counts_kernel() {
    __shared__ int cnt;
    if (threadIdx.x == 0) cnt = 0;
    __syncthreads();
    int e = blockIdx.x;
    int local = 0;
    for (int n = threadIdx.x; n < NTOK; n += 256)
        if (g_top_e[2*n] == e || g_top_e[2*n+1] == e) local++;
    atomicAdd(&cnt, local);
    __syncthreads();
    if (threadIdx.x == 0) g_counts[e] = cnt;
}

__global__ void offsets_kernel() {
    int off = 0;
    for (int e = 0; e < EE; ++e) {
        g_pad_off[e] = off;
        int seg = ((g_counts[e] + 127) >> 7) << 7;
        int t0 = off >> 7, t1 = (off + seg) >> 7;
        for (int t = t0; t < t1; ++t) g_tile_expert[t] = e;
        off += seg;
    }
    g_pad_off[EE] = off;
    g_n_mtiles = off >> 7;
}

__global__ __launch_bounds__(128)
void compact_kernel() {
    int e = blockIdx.x;
    int tid = threadIdx.x;
    int lane = tid & 31, wid = tid >> 5;
    __shared__ int warp_cnt[4];
    __shared__ int running;
    if (tid == 0) running = 0;
    __syncthreads();
    int base = g_pad_off[e];
    for (int c = 0; c < NTOK / 128; ++c) {
        int n = c * 128 + tid;
        int k = -1;
        if (g_top_e[2*n] == e) k = 0;
        else if (g_top_e[2*n+1] == e) k = 1;
        unsigned msk = __ballot_sync(0xffffffffu, k >= 0);
        int rank = __popc(msk & ((1u << lane) - 1));
        if (lane == 0) warp_cnt[wid] = __popc(msk);
        __syncthreads();
        int wbase = 0;
        #pragma unroll
        for (int w = 0; w < 4; ++w) if (w < wid) wbase += warp_cnt[w];
        int cur = running;
        if (k >= 0) {
            int slot = base + cur + wbase + rank;
            g_tok_of_slot[slot] = n;
            g_slot_of[2*n + k]  = slot;
        }
        __syncthreads();
        if (tid == 0)
            running = cur + warp_cnt[0] + warp_cnt[1] + warp_cnt[2] + warp_cnt[3];
        __syncthreads();
    }
    int cnt = running;
    int end = g_pad_off[e + 1];
    for (int s = base + cnt + tid; s < end; s += 128) g_tok_of_slot[s] = 0;
}

// ---------------- combine: out = x_resid + w0*y[s0] + w1*y[s1] ----------------
__global__ __launch_bounds__(256)
void combine_kernel(const float* __restrict__ xres, const float* __restrict__ y,
                    float* __restrict__ out) {
    int n = blockIdx.x;
    int s0 = g_slot_of[2*n], s1 = g_slot_of[2*n+1];
    float wa = g_top_w[2*n], wb = g_top_w[2*n+1];
    int tid = threadIdx.x;
    float4 a  = ((const float4*)(xres + (size_t)n  * DD))[tid];
    float4 y0 = ((const float4*)(y + (size_t)s0 * DD))[tid];
    float4 y1 = ((const float4*)(y + (size_t)s1 * DD))[tid];
    float4 r;
    r.x = a.x + wa * y0.x + wb * y1.x;
    r.y = a.y + wa * y0.y + wb * y1.y;
    r.z = a.z + wa * y0.z + wb * y1.z;
    r.w = a.w + wa * y0.w + wb * y1.w;
    ((float4*)(out + (size_t)n * DD))[tid] = r;
}

// ---------------- launch ----------------
extern "C" void kernel_launch(void* const* d_in, const int* in_sizes, int n_in,
                              void* d_out, int out_size) {
    const float* x      = (const float*)d_in[0];
    const float* ln1_g  = (const float*)d_in[1];
    const float* ln1_b  = (const float*)d_in[2];
    const float* ln2_g  = (const float*)d_in[3];
    const float* ln2_b  = (const float*)d_in[4];
    const float* w_qkv  = (const float*)d_in[5];
    const float* w_o    = (const float*)d_in[6];
    const float* w_gate = (const float*)d_in[7];
    const float* w1     = (const float*)d_in[8];
    const float* b1     = (const float*)d_in[9];
    const float* w2     = (const float*)d_in[10];
    const float* b2     = (const float*)d_in[11];
    float* out = (float*)d_out;

    float* p_hln;  cudaGetSymbolAddress((void**)&p_hln,  g_hln);
    float* p_qkv;  cudaGetSymbolAddress((void**)&p_qkv,  g_qkv);
    float* p_attn; cudaGetSymbolAddress((void**)&p_attn, g_attn);
    float* p_xres; cudaGetSymbolAddress((void**)&p_xres, g_xres);
    float* p_moein;cudaGetSymbolAddress((void**)&p_moein,g_moein);
    float* p_h1;   cudaGetSymbolAddress((void**)&p_h1,   g_h1);
    float* p_y;    cudaGetSymbolAddress((void**)&p_y,    g_y);

    // 1. LN1
    ln_kernel<<<NTOK, 256>>>(x, ln1_g, ln1_b, p_hln);
    // 2. QKV GEMM [4096,1024]x[1024,3072]
    sgemm_kernel<false><<<dim3(3 * DD / 128, NTOK / 128), 256>>>(
        p_hln, w_qkv, nullptr, p_qkv, NTOK, 3 * DD, DD);
    // 3. causal attention
    attn_kernel<<<dim3(SS / 64, HH, BB), 64>>>(p_qkv, p_attn);
    // 4. O-proj + residual
    sgemm_kernel<true><<<dim3(DD / 128, NTOK / 128), 256>>>(
        p_attn, w_o, x, p_xres, NTOK, DD, DD);
    // 5. LN2
    ln_kernel<<<NTOK, 256>>>(p_xres, ln2_g, ln2_b, p_moein);
    // 6. gate + top-2
    gate_kernel<<<NTOK / 4, 128>>>(p_moein, w_gate);
    // 7-9. routing
    counts_kernel<<<EE, 256>>>();
    offsets_kernel<<<1, 1>>>();
    compact_kernel<<<EE, 128>>>();
    // 10. expert GEMM1: gelu(x @ w1[e] + b1[e])
    moe_gemm_kernel<true><<<dim3(FF / 128, MAXMT), 256>>>(
        p_moein, w1, b1, p_h1, FF, DD);
    // 11. expert GEMM2: h1 @ w2[e] + b2[e]
    moe_gemm_kernel<false><<<dim3(DD / 128, MAXMT), 256>>>(
        p_h1, w2, b2, p_y, DD, FF);
    // 12. combine + residual
    combine_kernel<<<NTOK, 256>>>(p_xres, p_y, out);
}

// round 5
// speedup vs baseline: 2.6223x; 2.6223x over previous
#include <cuda_runtime.h>
#include <cuda_bf16.h>
#include <stdint.h>
#include <math.h>

// Problem constants
#define BB 8
#define SS 512
#define DD 1024
#define FF 4096
#define EE 8
#define HH 16
#define NTOK 4096              // B*S
#define NSLOT 8192             // NTOK * top2
#define MAXPAD 9216            // 8192 + 8*128 padding
#define MAXMT 72               // MAXPAD/128

// ---------------- scratch (device globals; no allocation) ----------------
__device__ float g_hln [NTOK * DD];
__device__ float g_qkv [NTOK * 3 * DD];
__device__ float g_attn[NTOK * DD];
__device__ float g_xres[NTOK * DD];
__device__ float g_moein[NTOK * DD];
__device__ float g_h1  [MAXPAD * FF];
__device__ float g_y   [MAXPAD * DD];

__device__ int   g_top_e[NSLOT];
__device__ float g_top_w[NSLOT];
__device__ int   g_counts[EE];
__device__ int   g_pad_off[EE + 1];
__device__ int   g_tile_expert[MAXMT];
__device__ int   g_n_mtiles;
__device__ int   g_tok_of_slot[MAXPAD];
__device__ int   g_slot_of[NSLOT];

// ---------------- helpers ----------------
__device__ __forceinline__ uint32_t smem_u32(const void* p) {
    uint32_t a;
    asm("{ .reg .u64 t; cvta.to.shared.u64 t, %1; cvt.u32.u64 %0, t; }" : "=r"(a) : "l"(p));
    return a;
}
__device__ __forceinline__ uint32_t f2tf(float f) {
    uint32_t u;
    asm("cvt.rna.tf32.f32 %0, %1;" : "=r"(u) : "f"(f));
    return u;
}
__device__ __forceinline__ float gelu_tanh(float v) {
    const float c = 0.7978845608028654f;
    float u = c * (v + 0.044715f * v * v * v);
    return 0.5f * v * (1.0f + tanhf(u));
}

// ============ tf32 mma.sync GEMM: 128x128 CTA tile, 256 thr, warp 32x64 ============
// MODE 0: C = A*B                      (QKV)
// MODE 1: C = A*B + aux (residual)     (O-proj)
// MODE 2: C = gelu(Agather*B1[e]+b1)   (MoE up; A rows via g_tok_of_slot)
// MODE 3: C = A*B2[e] + b2             (MoE down)
#define MM_SMEM_BYTES 65536

template<int MODE, int KDIM, int NDIM>
__global__ __launch_bounds__(256)
void gemm_mma(const float* __restrict__ A, const float* __restrict__ W,
              const float* __restrict__ aux, float* __restrict__ C) {
    int mt = blockIdx.y;
    if (MODE >= 2 && mt >= g_n_mtiles) return;
    const float* Wb = W;
    const float* bias = aux;
    if (MODE >= 2) {
        int e = g_tile_expert[mt];
        Wb   = W + (size_t)e * KDIM * NDIM;
        bias = aux + (size_t)e * NDIM;
    }
    extern __shared__ __align__(16) char smem[];   // buf b at b*32768: A 16KB, B 16KB

    int tid = threadIdx.x;
    int lane = tid & 31, wid = tid >> 5;
    int bm = mt * 128, bn = blockIdx.x * 128;

    // ---- gmem fill mapping ----
    // A: thread -> rows {rg, rg+32, rg+64, rg+96}, float4 at k-chunk cc
    int rg = tid >> 3, cc = tid & 7;
    const float* arow[4];
    #pragma unroll
    for (int i = 0; i < 4; i++) {
        int r = rg + i * 32;
        int m = (MODE == 2) ? g_tok_of_slot[bm + r] : (bm + r);
        arow[i] = A + (size_t)m * KDIM + cc * 4;
    }
    uint32_t a_sw = (uint32_t)(((cc ^ (rg & 7)) << 4) + rg * 128);
    // B transposed gather: thread -> n col nn, k-groups {kg0, kg0+2, kg0+4, kg0+6}
    int nn = tid & 127, kg0 = tid >> 7;
    const float* bcol = Wb + bn + nn;
    int n7 = nn & 7;

    // ---- fragment read bases (ldmatrix) ----
    uint32_t sbase = smem_u32(smem);
    int wr = wid & 3, wc = wid >> 2;                 // warp grid 4x2
    int rowa_base = wr * 32 + (lane & 7) + ((lane >> 3) & 1) * 8;
    int lhiA = lane >> 4;
    uint32_t aswz = (uint32_t)((rowa_base & 7) << 4);
    int rowb_base = wc * 64 + (lane & 7);
    int lbB = (lane >> 3) & 1;
    uint32_t bswz = (uint32_t)((lane & 7) << 4);

    float acc[2][8][4];
    #pragma unroll
    for (int mi = 0; mi < 2; mi++)
        #pragma unroll
        for (int ni = 0; ni < 8; ni++)
            #pragma unroll
            for (int j = 0; j < 4; j++) acc[mi][ni][j] = 0.f;

    float4 pa[4], pb[4];

    auto load_g = [&](int s) {
        int k0 = s * 32;
        #pragma unroll
        for (int i = 0; i < 4; i++) pa[i] = *(const float4*)(arow[i] + k0);
        #pragma unroll
        for (int tt = 0; tt < 4; tt++) {
            int kg = kg0 + tt * 2;
            size_t kk = (size_t)(k0 + kg * 4) * NDIM;
            float4 v;
            v.x = bcol[kk];
            v.y = bcol[kk + NDIM];
            v.z = bcol[kk + 2 * (size_t)NDIM];
            v.w = bcol[kk + 3 * (size_t)NDIM];
            pb[tt] = v;
        }
    };
    auto store_s = [&](int buf) {
        char* ab = smem + buf * 32768;
        char* bb = ab + 16384;
        #pragma unroll
        for (int i = 0; i < 4; i++) {
            uint4 u;
            u.x = f2tf(pa[i].x); u.y = f2tf(pa[i].y);
            u.z = f2tf(pa[i].z); u.w = f2tf(pa[i].w);
            *(uint4*)(ab + a_sw + i * (32 * 128)) = u;
        }
        #pragma unroll
        for (int tt = 0; tt < 4; tt++) {
            int kg = kg0 + tt * 2;
            uint4 u;
            u.x = f2tf(pb[tt].x); u.y = f2tf(pb[tt].y);
            u.z = f2tf(pb[tt].z); u.w = f2tf(pb[tt].w);
            *(uint4*)(bb + nn * 128 + ((kg ^ n7) << 4)) = u;
        }
    };
    auto compute = [&](int buf) {
        uint32_t abase = sbase + buf * 32768;
        uint32_t bbase = abase + 16384;
        #pragma unroll
        for (int ks = 0; ks < 4; ks++) {
            uint32_t af[2][4];
            #pragma unroll
            for (int mi = 0; mi < 2; mi++) {
                uint32_t addr = abase + (uint32_t)((rowa_base + mi * 16) * 128)
                              + ((((uint32_t)(ks * 2 + lhiA)) << 4) ^ aswz);
                asm volatile("ldmatrix.sync.aligned.m8n8.x4.shared.b16 {%0,%1,%2,%3}, [%4];"
                    : "=r"(af[mi][0]), "=r"(af[mi][1]), "=r"(af[mi][2]), "=r"(af[mi][3])
                    : "r"(addr));
            }
            uint32_t bf[8][2];
            #pragma unroll
            for (int ni = 0; ni < 8; ni++) {
                uint32_t addr = bbase + (uint32_t)((rowb_base + ni * 8) * 128)
                              + ((((uint32_t)(ks * 2 + lbB)) << 4) ^ bswz);
                asm volatile("ldmatrix.sync.aligned.m8n8.x2.shared.b16 {%0,%1}, [%2];"
                    : "=r"(bf[ni][0]), "=r"(bf[ni][1]) : "r"(addr));
            }
            #pragma unroll
            for (int mi = 0; mi < 2; mi++)
                #pragma unroll
                for (int ni = 0; ni < 8; ni++)
                    asm volatile("mma.sync.aligned.m16n8k8.row.col.f32.tf32.tf32.f32 "
                        "{%0,%1,%2,%3}, {%4,%5,%6,%7}, {%8,%9}, {%0,%1,%2,%3};"
                        : "+f"(acc[mi][ni][0]), "+f"(acc[mi][ni][1]),
                          "+f"(acc[mi][ni][2]), "+f"(acc[mi][ni][3])
                        : "r"(af[mi][0]), "r"(af[mi][1]), "r"(af[mi][2]), "r"(af[mi][3]),
                          "r"(bf[ni][0]), "r"(bf[ni][1]));
        }
    };

    const int NSTAGE = KDIM / 32;
    load_g(0);
    store_s(0);
    __syncthreads();
    for (int s = 0; s < NSTAGE; ++s) {
        int buf = s & 1;
        if (s + 1 < NSTAGE) load_g(s + 1);
        compute(buf);
        if (s + 1 < NSTAGE) store_s(buf ^ 1);
        __syncthreads();
    }

    // ---- epilogue (accumulators already in registers) ----
    int qr = lane >> 2, c2 = (lane & 3) * 2;
    #pragma unroll
    for (int mi = 0; mi < 2; mi++) {
        int r0 = bm + wr * 32 + mi * 16 + qr;
        #pragma unroll
        for (int ni = 0; ni < 8; ni++) {
            int col = bn + wc * 64 + ni * 8 + c2;
            float v0 = acc[mi][ni][0], v1 = acc[mi][ni][1];
            float v2 = acc[mi][ni][2], v3 = acc[mi][ni][3];
            if (MODE == 1) {
                float2 ra = *(const float2*)(aux + (size_t)r0 * NDIM + col);
                float2 rb = *(const float2*)(aux + (size_t)(r0 + 8) * NDIM + col);
                v0 += ra.x; v1 += ra.y; v2 += rb.x; v3 += rb.y;
            }
            if (MODE >= 2) {
                float2 bz = *(const float2*)(bias + col);
                v0 += bz.x; v1 += bz.y; v2 += bz.x; v3 += bz.y;
                if (MODE == 2) {
                    v0 = gelu_tanh(v0); v1 = gelu_tanh(v1);
                    v2 = gelu_tanh(v2); v3 = gelu_tanh(v3);
                }
            }
            *(float2*)(C + (size_t)r0 * NDIM + col)       = make_float2(v0, v1);
            *(float2*)(C + (size_t)(r0 + 8) * NDIM + col) = make_float2(v2, v3);
        }
    }
}

// ---------------- LayerNorm ----------------
__global__ __launch_bounds__(256)
void ln_kernel(const float* __restrict__ x, const float* __restrict__ g,
               const float* __restrict__ b, float* __restrict__ y) {
    int n = blockIdx.x;
    int tid = threadIdx.x;
    const float4* xr = (const float4*)(x + (size_t)n * DD);
    float4 v = xr[tid];
    float s  = v.x + v.y + v.z + v.w;
    float sq = v.x*v.x + v.y*v.y + v.z*v.z + v.w*v.w;
    __shared__ float red[2][8];
    int lane = tid & 31, wid = tid >> 5;
    #pragma unroll
    for (int o = 16; o > 0; o >>= 1) {
        s  += __shfl_down_sync(0xffffffffu, s,  o);
        sq += __shfl_down_sync(0xffffffffu, sq, o);
    }
    if (lane == 0) { red[0][wid] = s; red[1][wid] = sq; }
    __syncthreads();
    if (wid == 0) {
        float a = (lane < 8) ? red[0][lane] : 0.f;
        float c = (lane < 8) ? red[1][lane] : 0.f;
        #pragma unroll
        for (int o = 4; o > 0; o >>= 1) {
            a += __shfl_down_sync(0xffffffffu, a, o);
            c += __shfl_down_sync(0xffffffffu, c, o);
        }
        if (lane == 0) { red[0][0] = a; red[1][0] = c; }
    }
    __syncthreads();
    float mean = red[0][0] * (1.0f / DD);
    float var  = red[1][0] * (1.0f / DD) - mean * mean;
    float rstd = rsqrtf(var + 1e-5f);
    float4 gv = ((const float4*)g)[tid];
    float4 bv = ((const float4*)b)[tid];
    float4 o;
    o.x = (v.x - mean) * rstd * gv.x + bv.x;
    o.y = (v.y - mean) * rstd * gv.y + bv.y;
    o.z = (v.z - mean) * rstd * gv.z + bv.z;
    o.w = (v.w - mean) * rstd * gv.w + bv.w;
    ((float4*)(y + (size_t)n * DD))[tid] = o;
}

// ---------------- causal flash attention (fp32 SIMT) ----------------
__global__ __launch_bounds__(64)
void attn_kernel(const float* __restrict__ qkv, float* __restrict__ o) {
    __shared__ float KV[64][64];
    __shared__ float Sb[64][65];
    int qt = blockIdx.x, h = blockIdx.y, b = blockIdx.z;
    int t = threadIdx.x;
    int q = qt * 64 + t;
    const float* qrow = qkv + (size_t)(b * SS + q) * (3 * DD) + h * 64;
    float qreg[64];
    #pragma unroll
    for (int d = 0; d < 64; d++) qreg[d] = qrow[d];
    float acc[64];
    #pragma unroll
    for (int d = 0; d < 64; d++) acc[d] = 0.f;
    float m = -1e30f, l = 0.f;
    const float scale = 0.125f;
    for (int kt = 0; kt <= qt; ++kt) {
        for (int i = t; i < 1024; i += 64) {
            int j = i * 4; int kk = j >> 6; int d = j & 63;
            *(float4*)&KV[kk][d] = *(const float4*)(
                qkv + (size_t)(b * SS + kt * 64 + kk) * (3 * DD) + DD + h * 64 + d);
        }
        __syncthreads();
        int kmax = (kt == qt) ? (t + 1) : 64;
        float tmax = -1e30f;
        for (int kk = 0; kk < kmax; ++kk) {
            float s = 0.f;
            #pragma unroll
            for (int d = 0; d < 64; d++) s += qreg[d] * KV[kk][d];
            s *= scale;
            Sb[t][kk] = s;
            tmax = fmaxf(tmax, s);
        }
        float mn = fmaxf(m, tmax);
        float corr = __expf(m - mn);
        #pragma unroll
        for (int d = 0; d < 64; d++) acc[d] *= corr;
        l *= corr;
        m = mn;
        __syncthreads();
        for (int i = t; i < 1024; i += 64) {
            int j = i * 4; int kk = j >> 6; int d = j & 63;
            *(float4*)&KV[kk][d] = *(const float4*)(
                qkv + (size_t)(b * SS + kt * 64 + kk) * (3 * DD) + 2 * DD + h * 64 + d);
        }
        __syncthreads();
        for (int kk = 0; kk < kmax; ++kk) {
            float p = __expf(Sb[t][kk] - m);
            l += p;
            #pragma unroll
            for (int d = 0; d < 64; d++) acc[d] += p * KV[kk][d];
        }
        __syncthreads();
    }
    float inv = 1.f / l;
    float* orow = o + (size_t)(b * SS + q) * DD + h * 64;
    #pragma unroll
    for (int d = 0; d < 64; d++) orow[d] = acc[d] * inv;
}

// ---------------- gate: logits + top-2 ----------------
__global__ __launch_bounds__(128)
void gate_kernel(const float* __restrict__ moe_in, const float* __restrict__ w_gate) {
    int lane = threadIdx.x & 31, wid = threadIdx.x >> 5;
    int n = blockIdx.x * 4 + wid;
    float acc[EE];
    #pragma unroll
    for (int e = 0; e < EE; e++) acc[e] = 0.f;
    const float* xr = moe_in + (size_t)n * DD;
    for (int d = lane; d < DD; d += 32) {
        float xv = xr[d];
        const float* wg = w_gate + (size_t)d * EE;
        #pragma unroll
        for (int e = 0; e < EE; e++) acc[e] += xv * wg[e];
    }
    #pragma unroll
    for (int e = 0; e < EE; e++) {
        #pragma unroll
        for (int o = 16; o > 0; o >>= 1)
            acc[e] += __shfl_down_sync(0xffffffffu, acc[e], o);
    }
    if (lane == 0) {
        int i0 = 0;
        #pragma unroll
        for (int e = 1; e < EE; e++) if (acc[e] > acc[i0]) i0 = e;
        int i1 = (i0 == 0) ? 1 : 0;
        #pragma unroll
        for (int e = 0; e < EE; e++)
            if (e != i0 && acc[e] > acc[i1]) i1 = e;
        float w0 = 1.f / (1.f + __expf(acc[i1] - acc[i0]));
        g_top_e[2*n]   = i0;  g_top_e[2*n+1]   = i1;
        g_top_w[2*n]   = w0;  g_top_w[2*n+1]   = 1.f - w0;
    }
}

// ---------------- routing ----------------
__global__ void counts_kernel() {
    __shared__ int cnt;
    if (threadIdx.x == 0) cnt = 0;
    __syncthreads();
    int e = blockIdx.x;
    int local = 0;
    for (int n = threadIdx.x; n < NTOK; n += 256)
        if (g_top_e[2*n] == e || g_top_e[2*n+1] == e) local++;
    atomicAdd(&cnt, local);
    __syncthreads();
    if (threadIdx.x == 0) g_counts[e] = cnt;
}

__global__ void offsets_kernel() {
    int off = 0;
    for (int e = 0; e < EE; ++e) {
        g_pad_off[e] = off;
        int seg = ((g_counts[e] + 127) >> 7) << 7;
        int t0 = off >> 7, t1 = (off + seg) >> 7;
        for (int t = t0; t < t1; ++t) g_tile_expert[t] = e;
        off += seg;
    }
    g_pad_off[EE] = off;
    g_n_mtiles = off >> 7;
}

__global__ __launch_bounds__(128)
void compact_kernel() {
    int e = blockIdx.x;
    int tid = threadIdx.x;
    int lane = tid & 31, wid = tid >> 5;
    __shared__ int warp_cnt[4];
    __shared__ int running;
    if (tid == 0) running = 0;
    __syncthreads();
    int base = g_pad_off[e];
    for (int c = 0; c < NTOK / 128; ++c) {
        int n = c * 128 + tid;
        int k = -1;
        if (g_top_e[2*n] == e) k = 0;
        else if (g_top_e[2*n+1] == e) k = 1;
        unsigned msk = __ballot_sync(0xffffffffu, k >= 0);
        int rank = __popc(msk & ((1u << lane) - 1));
        if (lane == 0) warp_cnt[wid] = __popc(msk);
        __syncthreads();
        int wbase = 0;
        #pragma unroll
        for (int w = 0; w < 4; ++w) if (w < wid) wbase += warp_cnt[w];
        int cur = running;
        if (k >= 0) {
            int slot = base + cur + wbase + rank;
            g_tok_of_slot[slot] = n;
            g_slot_of[2*n + k]  = slot;
        }
        __syncthreads();
        if (tid == 0)
            running = cur + warp_cnt[0] + warp_cnt[1] + warp_cnt[2] + warp_cnt[3];
        __syncthreads();
    }
    int cnt = running;
    int end = g_pad_off[e + 1];
    for (int s = base + cnt + tid; s < end; s += 128) g_tok_of_slot[s] = 0;
}

// ---------------- combine ----------------
__global__ __launch_bounds__(256)
void combine_kernel(const float* __restrict__ xres, const float* __restrict__ y,
                    float* __restrict__ out) {
    int n = blockIdx.x;
    int s0 = g_slot_of[2*n], s1 = g_slot_of[2*n+1];
    float wa = g_top_w[2*n], wb = g_top_w[2*n+1];
    int tid = threadIdx.x;
    float4 a  = ((const float4*)(xres + (size_t)n  * DD))[tid];
    float4 y0 = ((const float4*)(y + (size_t)s0 * DD))[tid];
    float4 y1 = ((const float4*)(y + (size_t)s1 * DD))[tid];
    float4 r;
    r.x = a.x + wa * y0.x + wb * y1.x;
    r.y = a.y + wa * y0.y + wb * y1.y;
    r.z = a.z + wa * y0.z + wb * y1.z;
    r.w = a.w + wa * y0.w + wb * y1.w;
    ((float4*)(out + (size_t)n * DD))[tid] = r;
}

// ---------------- launch ----------------
extern "C" void kernel_launch(void* const* d_in, const int* in_sizes, int n_in,
                              void* d_out, int out_size) {
    const float* x      = (const float*)d_in[0];
    const float* ln1_g  = (const float*)d_in[1];
    const float* ln1_b  = (const float*)d_in[2];
    const float* ln2_g  = (const float*)d_in[3];
    const float* ln2_b  = (const float*)d_in[4];
    const float* w_qkv  = (const float*)d_in[5];
    const float* w_o    = (const float*)d_in[6];
    const float* w_gate = (const float*)d_in[7];
    const float* w1     = (const float*)d_in[8];
    const float* b1     = (const float*)d_in[9];
    const float* w2     = (const float*)d_in[10];
    const float* b2     = (const float*)d_in[11];
    float* out = (float*)d_out;

    float* p_hln;  cudaGetSymbolAddress((void**)&p_hln,  g_hln);
    float* p_qkv;  cudaGetSymbolAddress((void**)&p_qkv,  g_qkv);
    float* p_attn; cudaGetSymbolAddress((void**)&p_attn, g_attn);
    float* p_xres; cudaGetSymbolAddress((void**)&p_xres, g_xres);
    float* p_moein;cudaGetSymbolAddress((void**)&p_moein,g_moein);
    float* p_h1;   cudaGetSymbolAddress((void**)&p_h1,   g_h1);
    float* p_y;    cudaGetSymbolAddress((void**)&p_y,    g_y);

    cudaFuncSetAttribute(gemm_mma<0, DD, 3*DD>, cudaFuncAttributeMaxDynamicSharedMemorySize, MM_SMEM_BYTES);
    cudaFuncSetAttribute(gemm_mma<1, DD, DD>,   cudaFuncAttributeMaxDynamicSharedMemorySize, MM_SMEM_BYTES);
    cudaFuncSetAttribute(gemm_mma<2, DD, FF>,   cudaFuncAttributeMaxDynamicSharedMemorySize, MM_SMEM_BYTES);
    cudaFuncSetAttribute(gemm_mma<3, FF, DD>,   cudaFuncAttributeMaxDynamicSharedMemorySize, MM_SMEM_BYTES);

    // 1. LN1
    ln_kernel<<<NTOK, 256>>>(x, ln1_g, ln1_b, p_hln);
    // 2. QKV GEMM (tf32 mma.sync)
    gemm_mma<0, DD, 3*DD><<<dim3(3*DD/128, NTOK/128), 256, MM_SMEM_BYTES>>>(p_hln, w_qkv, nullptr, p_qkv);
    // 3. causal attention
    attn_kernel<<<dim3(SS/64, HH, BB), 64>>>(p_qkv, p_attn);
    // 4. O-proj + residual
    gemm_mma<1, DD, DD><<<dim3(DD/128, NTOK/128), 256, MM_SMEM_BYTES>>>(p_attn, w_o, x, p_xres);
    // 5. LN2
    ln_kernel<<<NTOK, 256>>>(p_xres, ln2_g, ln2_b, p_moein);
    // 6. gate + top-2
    gate_kernel<<<NTOK/4, 128>>>(p_moein, w_gate);
    // 7-9. routing
    counts_kernel<<<EE, 256>>>();
    offsets_kernel<<<1, 1>>>();
    compact_kernel<<<EE, 128>>>();
    // 10. MoE up: gelu(x @ w1[e] + b1[e])
    gemm_mma<2, DD, FF><<<dim3(FF/128, MAXMT), 256, MM_SMEM_BYTES>>>(p_moein, w1, b1, p_h1);
    // 11. MoE down: h1 @ w2[e] + b2[e]
    gemm_mma<3, FF, DD><<<dim3(DD/128, MAXMT), 256, MM_SMEM_BYTES>>>(p_h1, w2, b2, p_y);
    // 12. combine + residual
    combine_kernel<<<NTOK, 256>>>(p_xres, p_y, out);
}